// round 1
// baseline (speedup 1.0000x reference)
#include <cuda_runtime.h>
#include <math.h>

// ---- problem constants ----
#define BATCH   8
#define TT      256
#define BT      2048          // BATCH*TT
#define DM      256           // d_model
#define DI      512           // d_inner
#define DS      16            // d_state
#define DTR     16            // dt_rank
#define DBC     48            // DTR + 2*DS

// ---- scratch (device globals; no allocation allowed) ----
__device__ float g_f1[2048*16*32*32];   // conv1 out
__device__ float g_f2[2048*32*16*16];   // conv2 out
__device__ float g_z1[2048*32];         // pooled CNN features
__device__ float g_h [BT*DM];           // residual stream
__device__ float g_xn[BT*DM];           // rmsnorm output
__device__ float g_xz[BT*2*DI];         // in_proj output (xin | z)
__device__ float g_xin[BT*DI];          // conv1d+silu output
__device__ float g_dbc[BT*DBC];         // x_proj output
__device__ float g_delta[BT*DI];        // softplus(dt_proj)
__device__ float g_y [BT*DI];           // scan output gated
__device__ float g_hh[BT*64];           // head hidden
__device__ float g_logits[BT];

// =====================================================================
// CNN
// =====================================================================
__global__ void conv1_kernel(const float* __restrict__ x,
                             const float* __restrict__ w,
                             const float* __restrict__ b,
                             float* __restrict__ out)
{
    // x: (2048,1,64,64) -> out: (2048,16,32,32), stride2 SAME (pad lo=0 hi=1), relu
    __shared__ float sin[65*65];
    __shared__ float sw[16*9];
    __shared__ float sb[16];
    int f = blockIdx.x;
    const float* xf = x + (size_t)f*4096;
    for (int i = threadIdx.x; i < 65*65; i += blockDim.x) {
        int r = i / 65, c = i % 65;
        sin[i] = (r < 64 && c < 64) ? xf[r*64+c] : 0.f;
    }
    for (int i = threadIdx.x; i < 144; i += blockDim.x) sw[i] = w[i];
    if (threadIdx.x < 16) sb[threadIdx.x] = b[threadIdx.x];
    __syncthreads();
    for (int idx = threadIdx.x; idx < 16384; idx += blockDim.x) {
        int co = idx >> 10;
        int oy = (idx >> 5) & 31;
        int ox = idx & 31;
        const float* wc = sw + co*9;
        float acc = sb[co];
        int i0 = oy*2, j0 = ox*2;
        #pragma unroll
        for (int ky = 0; ky < 3; ky++)
            #pragma unroll
            for (int kx = 0; kx < 3; kx++)
                acc = fmaf(sin[(i0+ky)*65 + j0+kx], wc[ky*3+kx], acc);
        out[(size_t)f*16384 + idx] = fmaxf(acc, 0.f);
    }
}

__global__ void conv2_kernel(const float* __restrict__ in,
                             const float* __restrict__ w,
                             const float* __restrict__ b,
                             float* __restrict__ out)
{
    // in (2048,16,32,32) -> out (2048,32,16,16), grid (2048,2 halves in ox), 512 thr
    __shared__ float sin[16*33*17]; // 35.9KB
    int f  = blockIdx.x;
    int hx = blockIdx.y;
    for (int idx = threadIdx.x; idx < 16*33*17; idx += blockDim.x) {
        int ci = idx / (33*17);
        int rem = idx - ci*(33*17);
        int i = rem / 17, jl = rem - i*17;
        int j = hx*16 + jl;
        sin[idx] = (i < 32 && j < 32) ? in[(size_t)f*16384 + ci*1024 + i*32 + j] : 0.f;
    }
    __syncthreads();
    int co = threadIdx.x >> 4;     // 0..31
    int oy = threadIdx.x & 15;     // 0..15
    float acc[8];
    float bias = __ldg(&b[co]);
    #pragma unroll
    for (int q = 0; q < 8; q++) acc[q] = bias;
    #pragma unroll 1
    for (int ci = 0; ci < 16; ci++) {
        const float* wp = w + (co*16 + ci)*9;
        float w0 = __ldg(wp+0), w1 = __ldg(wp+1), w2 = __ldg(wp+2);
        float w3 = __ldg(wp+3), w4 = __ldg(wp+4), w5 = __ldg(wp+5);
        float w6 = __ldg(wp+6), w7 = __ldg(wp+7), w8 = __ldg(wp+8);
        const float* base = sin + ci*33*17;
        const float* r0 = base + (2*oy+0)*17;
        const float* r1 = base + (2*oy+1)*17;
        const float* r2 = base + (2*oy+2)*17;
        #pragma unroll
        for (int q = 0; q < 8; q++) {
            int j0 = 2*q;
            float a = acc[q];
            a = fmaf(r0[j0], w0, a); a = fmaf(r0[j0+1], w1, a); a = fmaf(r0[j0+2], w2, a);
            a = fmaf(r1[j0], w3, a); a = fmaf(r1[j0+1], w4, a); a = fmaf(r1[j0+2], w5, a);
            a = fmaf(r2[j0], w6, a); a = fmaf(r2[j0+1], w7, a); a = fmaf(r2[j0+2], w8, a);
            acc[q] = a;
        }
    }
    #pragma unroll
    for (int q = 0; q < 8; q++) {
        int ox = hx*8 + q;
        out[((size_t)f*32 + co)*256 + oy*16 + ox] = fmaxf(acc[q], 0.f);
    }
}

__global__ void conv3pool_kernel(const float* __restrict__ in,
                                 const float* __restrict__ w,
                                 const float* __restrict__ b,
                                 float* __restrict__ z1)
{
    // in (2048,32,16,16) -> conv (2048,32,8,8) relu -> mean over 8x8 -> z1 (2048,32)
    __shared__ float sin[32*17*17]; // 37KB
    int f = blockIdx.x;
    for (int idx = threadIdx.x; idx < 32*17*17; idx += blockDim.x) {
        int ci = idx / 289;
        int rem = idx - ci*289;
        int i = rem / 17, j = rem - i*17;
        sin[idx] = (i < 16 && j < 16) ? in[(size_t)f*8192 + ci*256 + i*16 + j] : 0.f;
    }
    __syncthreads();
    int co = threadIdx.x >> 3;   // 0..31
    int oy = threadIdx.x & 7;    // 0..7
    float acc[8];
    float bias = __ldg(&b[co]);
    #pragma unroll
    for (int q = 0; q < 8; q++) acc[q] = bias;
    #pragma unroll 1
    for (int ci = 0; ci < 32; ci++) {
        const float* wp = w + (co*32 + ci)*9;
        float w0 = __ldg(wp+0), w1 = __ldg(wp+1), w2 = __ldg(wp+2);
        float w3 = __ldg(wp+3), w4 = __ldg(wp+4), w5 = __ldg(wp+5);
        float w6 = __ldg(wp+6), w7 = __ldg(wp+7), w8 = __ldg(wp+8);
        const float* base = sin + ci*289;
        const float* r0 = base + (2*oy+0)*17;
        const float* r1 = base + (2*oy+1)*17;
        const float* r2 = base + (2*oy+2)*17;
        #pragma unroll
        for (int q = 0; q < 8; q++) {
            int j0 = 2*q;
            float a = acc[q];
            a = fmaf(r0[j0], w0, a); a = fmaf(r0[j0+1], w1, a); a = fmaf(r0[j0+2], w2, a);
            a = fmaf(r1[j0], w3, a); a = fmaf(r1[j0+1], w4, a); a = fmaf(r1[j0+2], w5, a);
            a = fmaf(r2[j0], w6, a); a = fmaf(r2[j0+1], w7, a); a = fmaf(r2[j0+2], w8, a);
            acc[q] = a;
        }
    }
    float s = 0.f;
    #pragma unroll
    for (int q = 0; q < 8; q++) s += fmaxf(acc[q], 0.f);
    // reduce across the 8 oy-threads of this co (consecutive lanes)
    #pragma unroll
    for (int o = 4; o > 0; o >>= 1) s += __shfl_down_sync(0xffffffffu, s, o, 8);
    if (oy == 0) z1[f*32 + co] = s * (1.f/64.f);
}

__global__ void fc_kernel(const float* __restrict__ z1,
                          const float* __restrict__ w,
                          const float* __restrict__ b,
                          float* __restrict__ h)
{
    int token = blockIdx.x;
    int j = threadIdx.x; // 256
    __shared__ float zr[32];
    if (j < 32) zr[j] = z1[token*32 + j];
    __syncthreads();
    const float* wr = w + j*32;
    float acc = b[j];
    #pragma unroll
    for (int k = 0; k < 32; k++) acc = fmaf(zr[k], wr[k], acc);
    h[token*256 + j] = acc;
}

// =====================================================================
// Mamba pieces
// =====================================================================
__global__ void rmsnorm_kernel(const float* __restrict__ x,
                               const float* __restrict__ w,
                               float* __restrict__ out)
{
    int t = blockIdx.x;
    int i = threadIdx.x; // 256
    float v = x[t*256 + i];
    float ss = v*v;
    #pragma unroll
    for (int o = 16; o > 0; o >>= 1) ss += __shfl_down_sync(0xffffffffu, ss, o);
    __shared__ float red[8];
    if ((i & 31) == 0) red[i >> 5] = ss;
    __syncthreads();
    if (i < 8) {
        float t2 = red[i];
        #pragma unroll
        for (int o = 4; o > 0; o >>= 1) t2 += __shfl_down_sync(0xffu, t2, o, 8);
        if (i == 0) red[0] = t2;
    }
    __syncthreads();
    float scale = rsqrtf(red[0] * (1.f/256.f) + 1e-5f);
    out[t*256 + i] = v * scale * w[i];
}

// C[M,N] (+)= A[M,K] * W[N,K]^T ; 64x64 tile, Kt=16, 256 threads, 4x4 microtile
template<bool ACC>
__global__ void gemm_nt_kernel(const float* __restrict__ A,
                               const float* __restrict__ W,
                               float* __restrict__ C,
                               int M, int N, int K)
{
    __shared__ float As[64][17];
    __shared__ float Ws[64][17];
    int bm = blockIdx.y * 64;
    int bn = blockIdx.x * 64;
    int tid = threadIdx.x;
    int lk = tid & 15;          // k within tile
    int lr = tid >> 4;          // 0..15
    int ty = tid >> 4;          // 0..15 (row group)
    int tx = tid & 15;          // 0..15 (col group)
    float acc[4][4] = {};
    for (int k0 = 0; k0 < K; k0 += 16) {
        #pragma unroll
        for (int s = 0; s < 4; s++) {
            int rr = lr + 16*s;
            As[rr][lk] = A[(size_t)(bm+rr)*K + k0 + lk];
            Ws[rr][lk] = W[(size_t)(bn+rr)*K + k0 + lk];
        }
        __syncthreads();
        #pragma unroll
        for (int k = 0; k < 16; k++) {
            float a[4], b[4];
            #pragma unroll
            for (int i = 0; i < 4; i++) a[i] = As[ty + 16*i][k];
            #pragma unroll
            for (int j = 0; j < 4; j++) b[j] = Ws[tx + 16*j][k];
            #pragma unroll
            for (int i = 0; i < 4; i++)
                #pragma unroll
                for (int j = 0; j < 4; j++)
                    acc[i][j] = fmaf(a[i], b[j], acc[i][j]);
        }
        __syncthreads();
    }
    #pragma unroll
    for (int i = 0; i < 4; i++) {
        int m = bm + ty + 16*i;
        #pragma unroll
        for (int j = 0; j < 4; j++) {
            int n = bn + tx + 16*j;
            size_t idx = (size_t)m*N + n;
            if (ACC) C[idx] += acc[i][j];
            else     C[idx]  = acc[i][j];
        }
    }
}

__global__ void conv1d_silu_kernel(const float* __restrict__ xz,
                                   const float* __restrict__ cw,
                                   const float* __restrict__ cb,
                                   float* __restrict__ xin)
{
    int idx = blockIdx.x * blockDim.x + threadIdx.x; // BT*DI
    int token = idx >> 9;
    int e = idx & 511;
    int t = token & 255;
    float acc = cb[e];
    const float* wk = cw + e*4;
    #pragma unroll
    for (int k = 0; k < 4; k++) {
        int tt = t - 3 + k;
        if (tt >= 0)
            acc = fmaf(xz[(size_t)(token - 3 + k)*1024 + e], wk[k], acc);
    }
    xin[idx] = acc / (1.f + expf(-acc));
}

__global__ void xproj_kernel(const float* __restrict__ xin,
                             const float* __restrict__ w,
                             float* __restrict__ dbc)
{
    // warp per output, outputs BT*48, K=512
    int wid = (blockIdx.x * blockDim.x + threadIdx.x) >> 5;
    int lane = threadIdx.x & 31;
    int token = wid / 48;
    int j = wid - token*48;
    const float* xr = xin + (size_t)token*512;
    const float* wr = w + (size_t)j*512;
    float acc = 0.f;
    #pragma unroll
    for (int k = lane; k < 512; k += 32) acc = fmaf(xr[k], wr[k], acc);
    #pragma unroll
    for (int o = 16; o > 0; o >>= 1) acc += __shfl_down_sync(0xffffffffu, acc, o);
    if (lane == 0) dbc[wid] = acc;
}

__global__ void dtproj_kernel(const float* __restrict__ dbc,
                              const float* __restrict__ dpw,
                              const float* __restrict__ dpb,
                              float* __restrict__ delta)
{
    int idx = blockIdx.x * blockDim.x + threadIdx.x; // BT*DI
    int token = idx >> 9;
    int e = idx & 511;
    const float* dr = dbc + token*48;
    const float* wr = dpw + e*16;
    float acc = dpb[e];
    #pragma unroll
    for (int k = 0; k < 16; k++) acc = fmaf(dr[k], wr[k], acc);
    // softplus
    float sp = (acc > 20.f) ? acc : log1pf(expf(acc));
    delta[idx] = sp;
}

__global__ void scan_kernel(const float* __restrict__ xin,
                            const float* __restrict__ xz,
                            const float* __restrict__ delta,
                            const float* __restrict__ dbc,
                            const float* __restrict__ A_log,
                            const float* __restrict__ Dp,
                            float* __restrict__ yout)
{
    int tid = blockIdx.x * blockDim.x + threadIdx.x;
    int ch = tid >> 4;           // 0..4095 = b*512 + e
    int n = tid & 15;
    int b = ch >> 9;
    int e = ch & 511;
    float A  = -expf(A_log[e*16 + n]);
    float Dv = Dp[e];
    float h = 0.f;
    int tok0 = b * 256;
    for (int t = 0; t < 256; t++) {
        int tok = tok0 + t;
        float dv = delta[(size_t)tok*512 + e];
        float u  = xin[(size_t)tok*512 + e];
        float Bn = dbc[tok*48 + 16 + n];
        float Cn = dbc[tok*48 + 32 + n];
        float dA = expf(dv * A);
        h = fmaf(h, dA, dv * Bn * u);
        float part = h * Cn;
        #pragma unroll
        for (int o = 8; o > 0; o >>= 1) part += __shfl_down_sync(0xffffffffu, part, o, 16);
        if (n == 0) {
            float zv = xz[(size_t)tok*1024 + 512 + e];
            float y = part + u * Dv;
            yout[(size_t)tok*512 + e] = y * (zv / (1.f + expf(-zv)));
        }
    }
}

// =====================================================================
// Head
// =====================================================================
__global__ void head1_kernel(const float* __restrict__ xn,
                             const float* __restrict__ w,
                             const float* __restrict__ b,
                             float* __restrict__ hh)
{
    // warp per output; outputs BT*64, K=256; gelu(tanh approx)
    int wid = (blockIdx.x * blockDim.x + threadIdx.x) >> 5;
    int lane = threadIdx.x & 31;
    int token = wid >> 6;
    int j = wid & 63;
    const float* xr = xn + (size_t)token*256;
    const float* wr = w + (size_t)j*256;
    float acc = 0.f;
    #pragma unroll
    for (int k = lane; k < 256; k += 32) acc = fmaf(xr[k], wr[k], acc);
    #pragma unroll
    for (int o = 16; o > 0; o >>= 1) acc += __shfl_down_sync(0xffffffffu, acc, o);
    if (lane == 0) {
        float v = acc + b[j];
        float v3 = v*v*v;
        float g = 0.5f * v * (1.f + tanhf(0.7978845608028654f * (v + 0.044715f*v3)));
        hh[wid] = g;
    }
}

__global__ void head2_kernel(const float* __restrict__ hh,
                             const float* __restrict__ w,
                             const float* __restrict__ b,
                             float* __restrict__ logits)
{
    // warp per token; K=64
    int wid = (blockIdx.x * blockDim.x + threadIdx.x) >> 5;
    int lane = threadIdx.x & 31;
    const float* xr = hh + (size_t)wid*64;
    float acc = fmaf(xr[lane], w[lane], xr[lane+32]*w[lane+32]);
    #pragma unroll
    for (int o = 16; o > 0; o >>= 1) acc += __shfl_down_sync(0xffffffffu, acc, o);
    if (lane == 0) logits[wid] = acc + b[0];
}

__global__ void softmax_kernel(const float* __restrict__ logits,
                               float* __restrict__ out)
{
    int b = blockIdx.x;
    int t = threadIdx.x; // 256
    float v = logits[b*256 + t];
    __shared__ float red[8];
    __shared__ float sM, sS;
    float m = v;
    #pragma unroll
    for (int o = 16; o > 0; o >>= 1) m = fmaxf(m, __shfl_xor_sync(0xffffffffu, m, o));
    if ((t & 31) == 0) red[t >> 5] = m;
    __syncthreads();
    if (t < 8) {
        float mm = red[t];
        #pragma unroll
        for (int o = 4; o > 0; o >>= 1) mm = fmaxf(mm, __shfl_xor_sync(0xffu, mm, o, 8));
        if (t == 0) sM = mm;
    }
    __syncthreads();
    float e = expf(v - sM);
    float s = e;
    #pragma unroll
    for (int o = 16; o > 0; o >>= 1) s += __shfl_xor_sync(0xffffffffu, s, o);
    __syncthreads();
    if ((t & 31) == 0) red[t >> 5] = s;
    __syncthreads();
    if (t < 8) {
        float ss2 = red[t];
        #pragma unroll
        for (int o = 4; o > 0; o >>= 1) ss2 += __shfl_xor_sync(0xffu, ss2, o, 8);
        if (t == 0) sS = ss2;
    }
    __syncthreads();
    out[b*256 + t] = (t == 0) ? 0.f : e / sS;
}

// =====================================================================
// Launcher
// =====================================================================
extern "C" void kernel_launch(void* const* d_in, const int* in_sizes, int n_in,
                              void* d_out, int out_size)
{
    (void)in_sizes; (void)n_in; (void)out_size;
    const float* x        = (const float*)d_in[0];
    const float* cnn_w1   = (const float*)d_in[1];
    const float* cnn_b1   = (const float*)d_in[2];
    const float* cnn_w2   = (const float*)d_in[3];
    const float* cnn_b2   = (const float*)d_in[4];
    const float* cnn_w3   = (const float*)d_in[5];
    const float* cnn_b3   = (const float*)d_in[6];
    const float* fc_w     = (const float*)d_in[7];
    const float* fc_b     = (const float*)d_in[8];
    const float* norm_w   = (const float*)d_in[9];
    const float* in_proj_w= (const float*)d_in[10];
    const float* conv1d_w = (const float*)d_in[11];
    const float* conv1d_b = (const float*)d_in[12];
    const float* x_proj_w = (const float*)d_in[13];
    const float* dt_proj_w= (const float*)d_in[14];
    const float* dt_proj_b= (const float*)d_in[15];
    const float* A_log    = (const float*)d_in[16];
    const float* Dp       = (const float*)d_in[17];
    const float* out_proj_w=(const float*)d_in[18];
    const float* norm_f_w = (const float*)d_in[19];
    const float* head_w1  = (const float*)d_in[20];
    const float* head_b1  = (const float*)d_in[21];
    const float* head_w2  = (const float*)d_in[22];
    const float* head_b2  = (const float*)d_in[23];
    float* out = (float*)d_out;

    float *f1, *f2, *z1, *h, *xn, *xz, *xin, *dbc, *delta, *y, *hh, *logits;
    cudaGetSymbolAddress((void**)&f1, g_f1);
    cudaGetSymbolAddress((void**)&f2, g_f2);
    cudaGetSymbolAddress((void**)&z1, g_z1);
    cudaGetSymbolAddress((void**)&h,  g_h);
    cudaGetSymbolAddress((void**)&xn, g_xn);
    cudaGetSymbolAddress((void**)&xz, g_xz);
    cudaGetSymbolAddress((void**)&xin,g_xin);
    cudaGetSymbolAddress((void**)&dbc,g_dbc);
    cudaGetSymbolAddress((void**)&delta,g_delta);
    cudaGetSymbolAddress((void**)&y,  g_y);
    cudaGetSymbolAddress((void**)&hh, g_hh);
    cudaGetSymbolAddress((void**)&logits, g_logits);

    // --- CNN encoder ---
    conv1_kernel<<<2048, 256>>>(x, cnn_w1, cnn_b1, f1);
    conv2_kernel<<<dim3(2048, 2), 512>>>(f1, cnn_w2, cnn_b2, f2);
    conv3pool_kernel<<<2048, 256>>>(f2, cnn_w3, cnn_b3, z1);
    fc_kernel<<<2048, 256>>>(z1, fc_w, fc_b, h);

    // --- Mamba layers ---
    for (int l = 0; l < 6; l++) {
        const float* nw  = norm_w     + (size_t)l*DM;
        const float* ipw = in_proj_w  + (size_t)l*2*DI*DM;
        const float* cw  = conv1d_w   + (size_t)l*DI*4;
        const float* cb  = conv1d_b   + (size_t)l*DI;
        const float* xpw = x_proj_w   + (size_t)l*DBC*DI;
        const float* dpw = dt_proj_w  + (size_t)l*DI*DTR;
        const float* dpb = dt_proj_b  + (size_t)l*DI;
        const float* al  = A_log      + (size_t)l*DI*DS;
        const float* dv  = Dp         + (size_t)l*DI;
        const float* opw = out_proj_w + (size_t)l*DM*DI;

        rmsnorm_kernel<<<BT, 256>>>(h, nw, xn);
        gemm_nt_kernel<false><<<dim3(1024/64, BT/64), 256>>>(xn, ipw, xz, BT, 1024, 256);
        conv1d_silu_kernel<<<BT*DI/256, 256>>>(xz, cw, cb, xin);
        xproj_kernel<<<BT*48*32/256, 256>>>(xin, xpw, dbc);
        dtproj_kernel<<<BT*DI/256, 256>>>(dbc, dpw, dpb, delta);
        scan_kernel<<<BATCH*DI*DS/256, 256>>>(xin, xz, delta, dbc, al, dv, y);
        gemm_nt_kernel<true><<<dim3(256/64, BT/64), 256>>>(y, opw, h, BT, 256, 512);
    }

    // --- Head ---
    rmsnorm_kernel<<<BT, 256>>>(h, norm_f_w, xn);
    head1_kernel<<<BT*64*32/256, 256>>>(xn, head_w1, head_b1, hh);
    head2_kernel<<<BT*32/256, 256>>>(hh, head_w2, head_b2, logits);
    softmax_kernel<<<BATCH, 256>>>(logits, out);
}